// round 15
// baseline (speedup 1.0000x reference)
#include <cuda_runtime.h>
#include <math.h>

#define Bn 8
#define Sn 256
#define TIN 10
#define WID 32
#define C0c 33
#define NT 24
#define NJ 48
#define NM 576
#define WSTRIDE (4*144*C0c*WID*2)

// -------- scratch (device globals; no allocation allowed) --------
__device__ float g_h0[(size_t)Bn*C0c*Sn*Sn];   // 69 MB
__device__ float g_h1[(size_t)Bn*WID*Sn*Sn];   // 67 MB
__device__ float g_X [(size_t)Bn*C0c*NM*2];
__device__ float g_OF[(size_t)Bn*WID*NM*2];
__device__ float g_G [(size_t)Bn*WID*Sn*NJ];
__device__ float g_wmix[(size_t)4*WSTRIDE];
__device__ float g_TFx[Sn*NJ];
__device__ float g_TFy[Sn*NJ];
__device__ float g_TGy[Sn*NJ];
__device__ float g_TWx[Sn*NJ];

// -------- packed f32x2 helpers (Blackwell FFMA2 path) --------
__device__ __forceinline__ void fma2(unsigned long long &d, unsigned long long a, unsigned long long b) {
    asm("fma.rn.f32x2 %0, %1, %2, %3;" : "=l"(d) : "l"(a), "l"(b), "l"(d));
}
__device__ __forceinline__ unsigned long long pk2(float x) {
    unsigned long long r;
    asm("mov.b64 %0, {%1, %1};" : "=l"(r) : "f"(x));
    return r;
}

// -------- fast erf-GELU (A&S 7.1.26, |erf err| < 2e-7; MUFU-offloaded) --------
__device__ __forceinline__ float fast_gelu(float x) {
    float z  = x * 0.70710678118654752f;
    float az = fabsf(z);
    float t  = __fdividef(1.0f, fmaf(0.3275911f, az, 1.0f));
    float p  = fmaf(1.061405429f, t, -1.453152027f);
    p = fmaf(p, t, 1.421413741f);
    p = fmaf(p, t, -0.284496736f);
    p = fmaf(p, t, 0.254829592f);
    p *= t;
    float e  = __expf(-z*z);
    float er = 1.0f - p*e;
    er = copysignf(er, z);
    float hx = 0.5f*x;
    return fmaf(hx, er, hx);
}

// -------- twiddle tables (exact via double sincospi) --------
__global__ void k_init() {
    int v = blockIdx.x; int j = threadIdx.x; int t = j >> 1; int im = j & 1;
    int kx = t < 12 ? t : 105 + t;
    int ky = t < 12 ? t : 232 + t;
    double s, c;
    sincospi(2.0 * kx * v / 256.0, &s, &c);
    g_TFx[v*NJ + j] = im ? (float)(-s) : (float)c;
    const double inv = 1.0 / 65536.0;
    double ar, bi;
    if (kx == 0)        { ar = inv;        bi = 0.0; }
    else if (kx == 128) { ar = c * inv;    bi = 0.0; }
    else                { ar = 2.0*c*inv;  bi = -2.0*s*inv; }
    g_TWx[v*NJ + j] = im ? (float)bi : (float)ar;
    sincospi(2.0 * ky * v / 256.0, &s, &c);
    g_TFy[v*NJ + j] = im ? (float)(-s) : (float)c;
    g_TGy[v*NJ + j] = im ? (float)s    : (float)c;
}

// -------- fc0 + grid concat + a_para concat + *a, to NCHW --------
__global__ void k_fc0(const float* __restrict__ x, const float* __restrict__ ap,
                      const float* __restrict__ w, const float* __restrict__ bias) {
    __shared__ float sw[12*32];
    __shared__ float sb[32];
    int tid = threadIdx.x;
    for (int i = tid; i < 384; i += 256) sw[i] = w[i];
    if (tid < 32)  sb[tid] = bias[tid];
    __syncthreads();
    int u = blockIdx.x, b = blockIdx.y, v = tid;
    const float* xp = x + (((size_t)b*Sn + u)*Sn + v)*TIN;
    float in[12];
    #pragma unroll
    for (int t = 0; t < 10; t++) in[t] = xp[t];
    in[10] = u * (1.0f/255.0f);
    in[11] = v * (1.0f/255.0f);
    float a = ap[((size_t)b*Sn + u)*Sn + v];
    float* hp = g_h0 + (size_t)b*C0c*Sn*Sn + (size_t)u*Sn + v;
    #pragma unroll 4
    for (int c = 0; c < 32; c++) {
        float acc = sb[c];
        #pragma unroll
        for (int t = 0; t < 12; t++) acc += in[t]*sw[t*32 + c];
        hp[(size_t)c*Sn*Sn] = acc * a;
    }
    hp[(size_t)32*Sn*Sn] = a * a;
}

// -------- repack rainbow weights for all 4 blocks in one launch --------
__global__ void k_wprep(const float* __restrict__ rb0, const float* __restrict__ rb1,
                        const float* __restrict__ rb2, const float* __restrict__ rb3) {
    int blk = blockIdx.y;
    const float* rb = blk == 0 ? rb0 : blk == 1 ? rb1 : blk == 2 ? rb2 : rb3;
    int Cin = blk == 0 ? C0c : WID;
    int total = 4*144*Cin*WID*2;
    float* wout = g_wmix + (size_t)blk*WSTRIDE;
    for (int i = blockIdx.x*blockDim.x + threadIdx.x; i < total; i += gridDim.x*blockDim.x) {
        int r = i & 1; int tmp = i >> 1;
        int co = tmp % WID; tmp /= WID;
        int ci = tmp % Cin; tmp /= Cin;
        int m = tmp % 144;  int q = tmp / 144;
        int m1 = m / 12, m2 = m % 12;
        wout[i] = rb[((((size_t)(q*Cin + ci)*WID + co)*12 + m1)*12 + m2)*2 + r];
    }
}

// -------- fused forward: T = h @ TFx (FFMA2 regs->smem), then X = Fy^T @ T --------
#define SM_FF (2*256*48*4)
__global__ __launch_bounds__(256) void k_ff(const float* __restrict__ src) {
    extern __shared__ float sm[];
    float* sT   = sm;            // 256 x 48
    float* sAux = sm + 256*48;   // B half (128x48) during f1; Fy (256x48) during f2
    int tid = threadIdx.x;
    size_t bc = blockIdx.x;
    const float* Abase = src + bc*(size_t)Sn*Sn;
    int jg = tid & 3, rowg = tid >> 2;
    int r0 = rowg*4;
    int j0 = jg*12;
    unsigned long long acc2[4][6] = {};   // 12 accumulators/row as 6 f32x2 pairs
    for (int half = 0; half < 2; half++) {
        __syncthreads();
        for (int i = tid; i < 128*48/4; i += 256)
            ((float4*)sAux)[i] = ((const float4*)(g_TFx + half*128*NJ))[i];
        __syncthreads();
        const float4* A0 = (const float4*)(Abase + (size_t)(r0+0)*256) + half*32;
        const float4* A1 = (const float4*)(Abase + (size_t)(r0+1)*256) + half*32;
        const float4* A2 = (const float4*)(Abase + (size_t)(r0+2)*256) + half*32;
        const float4* A3 = (const float4*)(Abase + (size_t)(r0+3)*256) + half*32;
        #pragma unroll 2
        for (int k4 = 0; k4 < 32; k4++) {
            float4 a0 = A0[k4], a1 = A1[k4], a2 = A2[k4], a3 = A3[k4];
            float av[4][4] = {{a0.x,a0.y,a0.z,a0.w},{a1.x,a1.y,a1.z,a1.w},
                              {a2.x,a2.y,a2.z,a2.w},{a3.x,a3.y,a3.z,a3.w}};
            #pragma unroll
            for (int kk = 0; kk < 4; kk++) {
                const ulonglong2* bp = (const ulonglong2*)(sAux + (k4*4 + kk)*48 + j0);
                ulonglong2 bA = bp[0], bB = bp[1], bC = bp[2];
                #pragma unroll
                for (int i = 0; i < 4; i++) {
                    unsigned long long p2 = pk2(av[i][kk]);
                    fma2(acc2[i][0], p2, bA.x);
                    fma2(acc2[i][1], p2, bA.y);
                    fma2(acc2[i][2], p2, bB.x);
                    fma2(acc2[i][3], p2, bB.y);
                    fma2(acc2[i][4], p2, bC.x);
                    fma2(acc2[i][5], p2, bC.y);
                }
            }
        }
    }
    #pragma unroll
    for (int i = 0; i < 4; i++) {
        ulonglong2* op = (ulonglong2*)(sT + (r0 + i)*48 + j0);
        ulonglong2 v0, v1, v2;
        v0.x = acc2[i][0]; v0.y = acc2[i][1];
        v1.x = acc2[i][2]; v1.y = acc2[i][3];
        v2.x = acc2[i][4]; v2.y = acc2[i][5];
        op[0] = v0; op[1] = v1; op[2] = v2;
    }
    __syncthreads();
    for (int i = tid; i < 3072; i += 256)
        ((float4*)sAux)[i] = ((const float4*)g_TFy)[i];
    __syncthreads();
    // f2 phase: 144 threads, each 2t x 2s (measured-best form, unchanged)
    if (tid < 144) {
        int tx = tid % 12, ty = tid / 12;
        float p0=0.f,p1=0.f,p2=0.f,p3=0.f;
        float q0=0.f,q1=0.f,q2=0.f,q3=0.f;
        #pragma unroll 4
        for (int u = 0; u < 256; u++) {
            float2 aA = *(const float2*)(sAux + u*NJ + 2*ty);
            float2 aB = *(const float2*)(sAux + u*NJ + 2*(ty+12));
            float4 tt = *(const float4*)(sT + u*NJ + 4*tx);
            p0 += aA.x*tt.x - aA.y*tt.y;  p1 += aA.x*tt.y + aA.y*tt.x;
            p2 += aA.x*tt.z - aA.y*tt.w;  p3 += aA.x*tt.w + aA.y*tt.z;
            q0 += aB.x*tt.x - aB.y*tt.y;  q1 += aB.x*tt.y + aB.y*tt.x;
            q2 += aB.x*tt.z - aB.y*tt.w;  q3 += aB.x*tt.w + aB.y*tt.z;
        }
        float4 oA; oA.x=p0; oA.y=p1; oA.z=p2; oA.w=p3;
        float4 oB; oB.x=q0; oB.y=q1; oB.z=q2; oB.w=q3;
        *((float4*)(g_X + (bc*NM + ty*24 + 2*tx)*2))      = oA;
        *((float4*)(g_X + (bc*NM + (ty+12)*24 + 2*tx)*2)) = oB;
    }
}

// -------- per-mode complex channel mixing: 4 modes per block --------
__global__ void k_mix(int Cin, int blk) {
    __shared__ float sx[4][C0c*2];
    int mode0 = blockIdx.x*4; int b = blockIdx.y;
    int tid = threadIdx.x;
    int sub = tid >> 5, co = tid & 31;
    for (int i = tid; i < 4*Cin*2; i += 128) {
        int ss = i / (Cin*2), ii = i % (Cin*2);
        sx[ss][ii] = g_X[(((size_t)b*Cin + (ii >> 1))*NM + mode0 + ss)*2 + (ii & 1)];
    }
    __syncthreads();
    int mode = mode0 + sub;
    int t = mode / 24, s = mode % 24;
    int q = (t >= 12 ? 1 : 0) + (s >= 12 ? 2 : 0);
    int m = (t % 12)*12 + (s % 12);
    const float2* wp = (const float2*)(g_wmix + (size_t)blk*WSTRIDE) + (size_t)(q*144 + m)*Cin*WID;
    float orr = 0.f, oi = 0.f;
    const float* xv = sx[sub];
    for (int ci = 0; ci < Cin; ci++) {
        float2 w = wp[ci*WID + co];
        float xr = xv[2*ci], xi = xv[2*ci + 1];
        orr += xr*w.x - xi*w.y;
        oi  += xr*w.y + xi*w.x;
    }
    g_OF[(((size_t)b*WID + co)*NM + mode)*2]     = orr;
    g_OF[(((size_t)b*WID + co)*NM + mode)*2 + 1] = oi;
}

// -------- inverse stage 1: ky-iDFT (24 -> 256 rows) --------
#define SM_I1 ((1152 + 256*49)*4)
__global__ __launch_bounds__(256) void k_i1() {
    extern __shared__ float sm[];
    float* sOF = sm;            // 1152
    float* sGy = sm + 1152;     // 256 x 49 (padded)
    int tid = threadIdx.x;
    size_t bc = blockIdx.x;     // b*32 + co
    for (int i = tid; i < NM*2; i += 256) sOF[i] = g_OF[bc*NM*2 + i];
    for (int i = tid; i < Sn*NJ; i += 256) {
        int u = i / NJ, j = i % NJ;
        sGy[u*49 + j] = g_TGy[i];
    }
    __syncthreads();
    int u = tid;
    const float* grow = sGy + u*49;
    float ar[24], ai[24];
    #pragma unroll
    for (int s = 0; s < 24; s++) { ar[s] = 0.f; ai[s] = 0.f; }
    #pragma unroll 1
    for (int t = 0; t < 24; t++) {
        float C = grow[2*t], S = grow[2*t + 1];
        const float2* ofp = (const float2*)(sOF + t*48);
        #pragma unroll
        for (int s = 0; s < 24; s++) {
            float2 of = ofp[s];
            ar[s] += C*of.x - S*of.y;
            ai[s] += C*of.y + S*of.x;
        }
    }
    float4* gp = (float4*)(g_G + (bc*Sn + u)*NJ);
    #pragma unroll
    for (int s4 = 0; s4 < 12; s4++) {
        float4 o; o.x = ar[2*s4]; o.y = ai[2*s4]; o.z = ar[2*s4+1]; o.w = ai[2*s4+1];
        gp[s4] = o;
    }
}

// -------- inverse stage 2 + 1x1 conv + bias + (gelu); co unrolled x2 --------
template<int CIN, bool DOGELU>
__global__ __launch_bounds__(256) void k_i2(const float* __restrict__ src, float* __restrict__ dst,
                     const float* __restrict__ cw, const float* __restrict__ cb) {
    __shared__ float sG[32*48];
    __shared__ float scw[32*36];
    __shared__ float scb[32];
    int tid = threadIdx.x;
    int u = blockIdx.x, b = blockIdx.y;
    for (int i = tid; i < 32*12; i += 256) {
        int co = i/12, j4 = i%12;
        ((float4*)(sG + co*48))[j4] =
            ((const float4*)(g_G + (((size_t)b*WID + co)*Sn + u)*NJ))[j4];
    }
    for (int i = tid; i < 32*CIN; i += 256)
        scw[(i/CIN)*36 + (i%CIN)] = cw[i];
    if (tid < 32) scb[tid] = cb[tid];
    float4 wr[12];
    {
        const float4* wp = (const float4*)(g_TWx + tid*NJ);
        #pragma unroll
        for (int q = 0; q < 12; q++) wr[q] = wp[q];
    }
    float r[CIN];
    #pragma unroll
    for (int ci = 0; ci < CIN; ci++)
        r[ci] = src[(((size_t)b*CIN + ci)*Sn + u)*Sn + tid];
    __syncthreads();
    #pragma unroll 1
    for (int co = 0; co < 32; co += 2) {
        const float4* gA = (const float4*)(sG + co*48);
        const float4* gB = (const float4*)(sG + (co+1)*48);
        const float4* wA = (const float4*)(scw + co*36);
        const float4* wB = (const float4*)(scw + (co+1)*36);
        float a0 = scb[co], a1 = 0.f, a2 = 0.f, a3 = 0.f;
        float b0 = scb[co+1], b1 = 0.f, b2 = 0.f, b3 = 0.f;
        #pragma unroll
        for (int j4 = 0; j4 < 12; j4++) {
            float4 ga = gA[j4], gb = gB[j4], w = wr[j4];
            a0 += ga.x*w.x; a1 += ga.y*w.y; a2 += ga.z*w.z; a3 += ga.w*w.w;
            b0 += gb.x*w.x; b1 += gb.y*w.y; b2 += gb.z*w.z; b3 += gb.w*w.w;
        }
        #pragma unroll
        for (int c4 = 0; c4 < CIN/4; c4++) {
            float4 wa = wA[c4], wb = wB[c4];
            float r0 = r[4*c4], r1 = r[4*c4+1], r2 = r[4*c4+2], r3 = r[4*c4+3];
            a0 += r0*wa.x; a1 += r1*wa.y; a2 += r2*wa.z; a3 += r3*wa.w;
            b0 += r0*wb.x; b1 += r1*wb.y; b2 += r2*wb.z; b3 += r3*wb.w;
        }
        if (CIN & 3) {
            #pragma unroll
            for (int ci = CIN & ~3; ci < CIN; ci++) {
                a0 += r[ci]*scw[co*36 + ci];
                b0 += r[ci]*scw[(co+1)*36 + ci];
            }
        }
        float accA = (a0 + a1) + (a2 + a3);
        float accB = (b0 + b1) + (b2 + b3);
        if (DOGELU) {
            accA = fast_gelu(accA);
            accB = fast_gelu(accB);
        }
        dst[(((size_t)b*WID + co)*Sn + u)*Sn + tid] = accA;
        dst[(((size_t)b*WID + co+1)*Sn + u)*Sn + tid] = accB;
    }
}

// -------- fused fc1 + gelu + fc2; 2 u-rows per block share W loads --------
__global__ __launch_bounds__(256) void k_fc12(const float* __restrict__ w1, const float* __restrict__ b1,
                       const float* __restrict__ w2, const float* __restrict__ b2,
                       float* __restrict__ out) {
    __shared__ float sW1t[128*32];   // [k][c]
    __shared__ float sW2[128];
    __shared__ float sB1[128];
    int tid = threadIdx.x;
    for (int i = tid; i < 4096; i += 256) {
        int c = i / 128, k = i % 128;
        sW1t[k*32 + c] = w1[i];
    }
    if (tid < 128) { sW2[tid] = w2[tid]; sB1[tid] = b1[tid]; }
    __syncthreads();
    int u0 = blockIdx.x*2, b = blockIdx.y, v = tid;
    float hv0[32], hv1[32];
    #pragma unroll
    for (int c = 0; c < 32; c++) {
        const float* hp = g_h0 + (((size_t)b*WID + c)*Sn + u0)*Sn + v;
        hv0[c] = hp[0];
        hv1[c] = hp[Sn];
    }
    float o0 = b2[0], o1 = b2[0];
    #pragma unroll 2
    for (int k = 0; k < 128; k++) {
        const float4* wk = (const float4*)(sW1t + k*32);
        float z0 = sB1[k], z1 = 0.f, z2 = 0.f, z3 = 0.f;
        float y0 = sB1[k], y1 = 0.f, y2 = 0.f, y3 = 0.f;
        #pragma unroll
        for (int c4 = 0; c4 < 8; c4++) {
            float4 w = wk[c4];
            z0 += hv0[4*c4]*w.x;   z1 += hv0[4*c4+1]*w.y;
            z2 += hv0[4*c4+2]*w.z; z3 += hv0[4*c4+3]*w.w;
            y0 += hv1[4*c4]*w.x;   y1 += hv1[4*c4+1]*w.y;
            y2 += hv1[4*c4+2]*w.z; y3 += hv1[4*c4+3]*w.w;
        }
        float z = fast_gelu((z0 + z1) + (z2 + z3));
        float y = fast_gelu((y0 + y1) + (y2 + y3));
        o0 += z*sW2[k];
        o1 += y*sW2[k];
    }
    out[((size_t)b*Sn + u0)*Sn + v]     = o0;
    out[((size_t)b*Sn + u0 + 1)*Sn + v] = o1;
}

// -------- host --------
extern "C" void kernel_launch(void* const* d_in, const int* in_sizes, int n_in,
                              void* d_out, int out_size) {
    const float* x    = (const float*)d_in[0];
    const float* ap   = (const float*)d_in[1];
    const float* fc0w = (const float*)d_in[2];
    const float* fc0b = (const float*)d_in[3];
    const float* rb[4] = {(const float*)d_in[4], (const float*)d_in[5],
                          (const float*)d_in[6], (const float*)d_in[7]};
    const float* cw[4] = {(const float*)d_in[8],  (const float*)d_in[10],
                          (const float*)d_in[12], (const float*)d_in[14]};
    const float* cb[4] = {(const float*)d_in[9],  (const float*)d_in[11],
                          (const float*)d_in[13], (const float*)d_in[15]};
    const float* fc1w = (const float*)d_in[16];
    const float* fc1b = (const float*)d_in[17];
    const float* fc2w = (const float*)d_in[18];
    const float* fc2b = (const float*)d_in[19];
    float* out = (float*)d_out;

    float *h0, *h1;
    cudaGetSymbolAddress((void**)&h0, g_h0);
    cudaGetSymbolAddress((void**)&h1, g_h1);

    cudaFuncSetAttribute(k_ff, cudaFuncAttributeMaxDynamicSharedMemorySize, SM_FF);
    cudaFuncSetAttribute(k_i1, cudaFuncAttributeMaxDynamicSharedMemorySize, SM_I1);

    k_init<<<256, 48>>>();
    k_wprep<<<dim3(256, 4), 256>>>(rb[0], rb[1], rb[2], rb[3]);
    k_fc0<<<dim3(Sn, Bn), 256>>>(x, ap, fc0w, fc0b);

    float* bufs[5] = {h0, h1, h0, h1, h0};
    for (int blk = 0; blk < 4; blk++) {
        int Cin = (blk == 0) ? 33 : 32;
        k_ff<<<Bn*Cin, 256, SM_FF>>>(bufs[blk]);
        k_mix<<<dim3(NM/4, Bn), 128>>>(Cin, blk);
        k_i1<<<Bn*WID, 256, SM_I1>>>();
        if (blk == 0)
            k_i2<33,true><<<dim3(Sn, Bn), 256>>>(bufs[0], bufs[1], cw[0], cb[0]);
        else if (blk < 3)
            k_i2<32,true><<<dim3(Sn, Bn), 256>>>(bufs[blk], bufs[blk+1], cw[blk], cb[blk]);
        else
            k_i2<32,false><<<dim3(Sn, Bn), 256>>>(bufs[3], bufs[4], cw[3], cb[3]);
    }
    k_fc12<<<dim3(Sn/2, Bn), 256>>>(fc1w, fc1b, fc2w, fc2b, out);
}

// round 17
// speedup vs baseline: 1.0271x; 1.0271x over previous
#include <cuda_runtime.h>
#include <math.h>

#define Bn 8
#define Sn 256
#define TIN 10
#define WID 32
#define C0c 33
#define NT 24
#define NJ 48
#define NM 576
#define WSTRIDE (4*144*C0c*WID*2)

// -------- scratch (device globals; no allocation allowed) --------
__device__ float g_h0[(size_t)Bn*C0c*Sn*Sn];   // 69 MB
__device__ float g_h1[(size_t)Bn*WID*Sn*Sn];   // 67 MB
__device__ float g_X [(size_t)Bn*C0c*NM*2];
__device__ float g_OF[(size_t)Bn*WID*NM*2];
__device__ float g_G [(size_t)Bn*WID*Sn*NJ];
__device__ float g_wmix[(size_t)4*WSTRIDE];
__device__ float g_TFx[Sn*NJ];
__device__ float g_TFy[Sn*NJ];
__device__ float g_TGy[Sn*NJ];
__device__ float g_TWx[Sn*NJ];

// -------- packed f32x2 helpers (Blackwell FFMA2 path) --------
__device__ __forceinline__ void fma2(unsigned long long &d, unsigned long long a, unsigned long long b) {
    asm("fma.rn.f32x2 %0, %1, %2, %3;" : "=l"(d) : "l"(a), "l"(b), "l"(d));
}
__device__ __forceinline__ unsigned long long pk2(float x) {
    unsigned long long r;
    asm("mov.b64 %0, {%1, %1};" : "=l"(r) : "f"(x));
    return r;
}
__device__ __forceinline__ unsigned long long pk2p(float lo, float hi) {
    unsigned long long r;
    asm("mov.b64 %0, {%1, %2};" : "=l"(r) : "f"(lo), "f"(hi));
    return r;
}
__device__ __forceinline__ void up2(unsigned long long p, float &lo, float &hi) {
    asm("mov.b64 {%0, %1}, %2;" : "=f"(lo), "=f"(hi) : "l"(p));
}

// -------- fast erf-GELU (A&S 7.1.26, |erf err| < 2e-7; MUFU-offloaded) --------
__device__ __forceinline__ float fast_gelu(float x) {
    float z  = x * 0.70710678118654752f;
    float az = fabsf(z);
    float t  = __fdividef(1.0f, fmaf(0.3275911f, az, 1.0f));
    float p  = fmaf(1.061405429f, t, -1.453152027f);
    p = fmaf(p, t, 1.421413741f);
    p = fmaf(p, t, -0.284496736f);
    p = fmaf(p, t, 0.254829592f);
    p *= t;
    float e  = __expf(-z*z);
    float er = 1.0f - p*e;
    er = copysignf(er, z);
    float hx = 0.5f*x;
    return fmaf(hx, er, hx);
}

// -------- twiddle tables (exact via double sincospi) --------
__global__ void k_init() {
    int v = blockIdx.x; int j = threadIdx.x; int t = j >> 1; int im = j & 1;
    int kx = t < 12 ? t : 105 + t;
    int ky = t < 12 ? t : 232 + t;
    double s, c;
    sincospi(2.0 * kx * v / 256.0, &s, &c);
    g_TFx[v*NJ + j] = im ? (float)(-s) : (float)c;
    const double inv = 1.0 / 65536.0;
    double ar, bi;
    if (kx == 0)        { ar = inv;        bi = 0.0; }
    else if (kx == 128) { ar = c * inv;    bi = 0.0; }
    else                { ar = 2.0*c*inv;  bi = -2.0*s*inv; }
    g_TWx[v*NJ + j] = im ? (float)bi : (float)ar;
    sincospi(2.0 * ky * v / 256.0, &s, &c);
    g_TFy[v*NJ + j] = im ? (float)(-s) : (float)c;
    g_TGy[v*NJ + j] = im ? (float)s    : (float)c;
}

// -------- fc0 + grid concat + a_para concat + *a, to NCHW --------
__global__ void k_fc0(const float* __restrict__ x, const float* __restrict__ ap,
                      const float* __restrict__ w, const float* __restrict__ bias) {
    __shared__ float sw[12*32];
    __shared__ float sb[32];
    int tid = threadIdx.x;
    for (int i = tid; i < 384; i += 256) sw[i] = w[i];
    if (tid < 32)  sb[tid] = bias[tid];
    __syncthreads();
    int u = blockIdx.x, b = blockIdx.y, v = tid;
    const float* xp = x + (((size_t)b*Sn + u)*Sn + v)*TIN;
    float in[12];
    #pragma unroll
    for (int t = 0; t < 10; t++) in[t] = xp[t];
    in[10] = u * (1.0f/255.0f);
    in[11] = v * (1.0f/255.0f);
    float a = ap[((size_t)b*Sn + u)*Sn + v];
    float* hp = g_h0 + (size_t)b*C0c*Sn*Sn + (size_t)u*Sn + v;
    #pragma unroll 4
    for (int c = 0; c < 32; c++) {
        float acc = sb[c];
        #pragma unroll
        for (int t = 0; t < 12; t++) acc += in[t]*sw[t*32 + c];
        hp[(size_t)c*Sn*Sn] = acc * a;
    }
    hp[(size_t)32*Sn*Sn] = a * a;
}

// -------- repack rainbow weights for all 4 blocks in one launch --------
__global__ void k_wprep(const float* __restrict__ rb0, const float* __restrict__ rb1,
                        const float* __restrict__ rb2, const float* __restrict__ rb3) {
    int blk = blockIdx.y;
    const float* rb = blk == 0 ? rb0 : blk == 1 ? rb1 : blk == 2 ? rb2 : rb3;
    int Cin = blk == 0 ? C0c : WID;
    int total = 4*144*Cin*WID*2;
    float* wout = g_wmix + (size_t)blk*WSTRIDE;
    for (int i = blockIdx.x*blockDim.x + threadIdx.x; i < total; i += gridDim.x*blockDim.x) {
        int r = i & 1; int tmp = i >> 1;
        int co = tmp % WID; tmp /= WID;
        int ci = tmp % Cin; tmp /= Cin;
        int m = tmp % 144;  int q = tmp / 144;
        int m1 = m / 12, m2 = m % 12;
        wout[i] = rb[((((size_t)(q*Cin + ci)*WID + co)*12 + m1)*12 + m2)*2 + r];
    }
}

// -------- fused forward: T = h @ TFx (FFMA2 regs->smem), then X = Fy^T @ T --------
#define SM_FF (2*256*48*4)
__global__ __launch_bounds__(256) void k_ff(const float* __restrict__ src) {
    extern __shared__ float sm[];
    float* sT   = sm;            // 256 x 48
    float* sAux = sm + 256*48;   // B half (128x48) during f1; Fy (256x48) during f2
    int tid = threadIdx.x;
    size_t bc = blockIdx.x;
    const float* Abase = src + bc*(size_t)Sn*Sn;
    int jg = tid & 3, rowg = tid >> 2;
    int r0 = rowg*4;
    int j0 = jg*12;
    unsigned long long acc2[4][6] = {};
    for (int half = 0; half < 2; half++) {
        __syncthreads();
        for (int i = tid; i < 128*48/4; i += 256)
            ((float4*)sAux)[i] = ((const float4*)(g_TFx + half*128*NJ))[i];
        __syncthreads();
        const float4* A0 = (const float4*)(Abase + (size_t)(r0+0)*256) + half*32;
        const float4* A1 = (const float4*)(Abase + (size_t)(r0+1)*256) + half*32;
        const float4* A2 = (const float4*)(Abase + (size_t)(r0+2)*256) + half*32;
        const float4* A3 = (const float4*)(Abase + (size_t)(r0+3)*256) + half*32;
        #pragma unroll 2
        for (int k4 = 0; k4 < 32; k4++) {
            float4 a0 = A0[k4], a1 = A1[k4], a2 = A2[k4], a3 = A3[k4];
            float av[4][4] = {{a0.x,a0.y,a0.z,a0.w},{a1.x,a1.y,a1.z,a1.w},
                              {a2.x,a2.y,a2.z,a2.w},{a3.x,a3.y,a3.z,a3.w}};
            #pragma unroll
            for (int kk = 0; kk < 4; kk++) {
                const ulonglong2* bp = (const ulonglong2*)(sAux + (k4*4 + kk)*48 + j0);
                ulonglong2 bA = bp[0], bB = bp[1], bC = bp[2];
                #pragma unroll
                for (int i = 0; i < 4; i++) {
                    unsigned long long p2 = pk2(av[i][kk]);
                    fma2(acc2[i][0], p2, bA.x);
                    fma2(acc2[i][1], p2, bA.y);
                    fma2(acc2[i][2], p2, bB.x);
                    fma2(acc2[i][3], p2, bB.y);
                    fma2(acc2[i][4], p2, bC.x);
                    fma2(acc2[i][5], p2, bC.y);
                }
            }
        }
    }
    #pragma unroll
    for (int i = 0; i < 4; i++) {
        ulonglong2* op = (ulonglong2*)(sT + (r0 + i)*48 + j0);
        ulonglong2 v0, v1, v2;
        v0.x = acc2[i][0]; v0.y = acc2[i][1];
        v1.x = acc2[i][2]; v1.y = acc2[i][3];
        v2.x = acc2[i][4]; v2.y = acc2[i][5];
        op[0] = v0; op[1] = v1; op[2] = v2;
    }
    __syncthreads();
    for (int i = tid; i < 3072; i += 256)
        ((float4*)sAux)[i] = ((const float4*)g_TFy)[i];
    __syncthreads();
    if (tid < 144) {
        int tx = tid % 12, ty = tid / 12;
        float p0=0.f,p1=0.f,p2=0.f,p3=0.f;
        float q0=0.f,q1=0.f,q2=0.f,q3=0.f;
        #pragma unroll 4
        for (int u = 0; u < 256; u++) {
            float2 aA = *(const float2*)(sAux + u*NJ + 2*ty);
            float2 aB = *(const float2*)(sAux + u*NJ + 2*(ty+12));
            float4 tt = *(const float4*)(sT + u*NJ + 4*tx);
            p0 += aA.x*tt.x - aA.y*tt.y;  p1 += aA.x*tt.y + aA.y*tt.x;
            p2 += aA.x*tt.z - aA.y*tt.w;  p3 += aA.x*tt.w + aA.y*tt.z;
            q0 += aB.x*tt.x - aB.y*tt.y;  q1 += aB.x*tt.y + aB.y*tt.x;
            q2 += aB.x*tt.z - aB.y*tt.w;  q3 += aB.x*tt.w + aB.y*tt.z;
        }
        float4 oA; oA.x=p0; oA.y=p1; oA.z=p2; oA.w=p3;
        float4 oB; oB.x=q0; oB.y=q1; oB.z=q2; oB.w=q3;
        *((float4*)(g_X + (bc*NM + ty*24 + 2*tx)*2))      = oA;
        *((float4*)(g_X + (bc*NM + (ty+12)*24 + 2*tx)*2)) = oB;
    }
}

// -------- per-mode complex channel mixing: 4 modes per block --------
__global__ void k_mix(int Cin, int blk) {
    __shared__ float sx[4][C0c*2];
    int mode0 = blockIdx.x*4; int b = blockIdx.y;
    int tid = threadIdx.x;
    int sub = tid >> 5, co = tid & 31;
    for (int i = tid; i < 4*Cin*2; i += 128) {
        int ss = i / (Cin*2), ii = i % (Cin*2);
        sx[ss][ii] = g_X[(((size_t)b*Cin + (ii >> 1))*NM + mode0 + ss)*2 + (ii & 1)];
    }
    __syncthreads();
    int mode = mode0 + sub;
    int t = mode / 24, s = mode % 24;
    int q = (t >= 12 ? 1 : 0) + (s >= 12 ? 2 : 0);
    int m = (t % 12)*12 + (s % 12);
    const float2* wp = (const float2*)(g_wmix + (size_t)blk*WSTRIDE) + (size_t)(q*144 + m)*Cin*WID;
    float orr = 0.f, oi = 0.f;
    const float* xv = sx[sub];
    for (int ci = 0; ci < Cin; ci++) {
        float2 w = wp[ci*WID + co];
        float xr = xv[2*ci], xi = xv[2*ci + 1];
        orr += xr*w.x - xi*w.y;
        oi  += xr*w.y + xi*w.x;
    }
    g_OF[(((size_t)b*WID + co)*NM + mode)*2]     = orr;
    g_OF[(((size_t)b*WID + co)*NM + mode)*2 + 1] = oi;
}

// -------- inverse stage 1: ky-iDFT (24 -> 256 rows) --------
#define SM_I1 ((1152 + 256*49)*4)
__global__ __launch_bounds__(256) void k_i1() {
    extern __shared__ float sm[];
    float* sOF = sm;            // 1152
    float* sGy = sm + 1152;     // 256 x 49 (padded)
    int tid = threadIdx.x;
    size_t bc = blockIdx.x;     // b*32 + co
    for (int i = tid; i < NM*2; i += 256) sOF[i] = g_OF[bc*NM*2 + i];
    for (int i = tid; i < Sn*NJ; i += 256) {
        int u = i / NJ, j = i % NJ;
        sGy[u*49 + j] = g_TGy[i];
    }
    __syncthreads();
    int u = tid;
    const float* grow = sGy + u*49;
    float ar[24], ai[24];
    #pragma unroll
    for (int s = 0; s < 24; s++) { ar[s] = 0.f; ai[s] = 0.f; }
    #pragma unroll 1
    for (int t = 0; t < 24; t++) {
        float C = grow[2*t], S = grow[2*t + 1];
        const float2* ofp = (const float2*)(sOF + t*48);
        #pragma unroll
        for (int s = 0; s < 24; s++) {
            float2 of = ofp[s];
            ar[s] += C*of.x - S*of.y;
            ai[s] += C*of.y + S*of.x;
        }
    }
    float4* gp = (float4*)(g_G + (bc*Sn + u)*NJ);
    #pragma unroll
    for (int s4 = 0; s4 < 12; s4++) {
        float4 o; o.x = ar[2*s4]; o.y = ai[2*s4]; o.z = ar[2*s4+1]; o.w = ai[2*s4+1];
        gp[s4] = o;
    }
}

// -------- inverse stage 2 + 1x1 conv + bias + (gelu); FFMA2 (wrp[24] FIXED) --------
template<int CIN, bool DOGELU>
__global__ __launch_bounds__(256) void k_i2(const float* __restrict__ src, float* __restrict__ dst,
                     const float* __restrict__ cw, const float* __restrict__ cb) {
    __shared__ float sG[32*48];
    __shared__ float scw[32*36];   // rows padded to 36 floats (144B = 9x16B aligned)
    __shared__ float scb[32];
    int tid = threadIdx.x;
    int u = blockIdx.x, b = blockIdx.y;
    for (int i = tid; i < 32*12; i += 256) {
        int co = i/12, j4 = i%12;
        ((float4*)(sG + co*48))[j4] =
            ((const float4*)(g_G + (((size_t)b*WID + co)*Sn + u)*NJ))[j4];
    }
    for (int i = tid; i < 32*CIN; i += 256)
        scw[(i/CIN)*36 + (i%CIN)] = cw[i];
    if (tid < 32) scb[tid] = cb[tid];
    // Wx row: 48 floats = 24 f32x2 pairs (FIX: was wrp[12] reading OOB)
    unsigned long long wrp[24];
    {
        const ulonglong2* wp = (const ulonglong2*)(g_TWx + tid*NJ);
        #pragma unroll
        for (int q = 0; q < 12; q++) {
            ulonglong2 w = wp[q];
            wrp[2*q] = w.x; wrp[2*q+1] = w.y;
        }
    }
    // src channels packed pairwise
    unsigned long long rp[CIN/2];
    float rtail = 0.f;
    {
        const float* sp = src + ((size_t)b*CIN*Sn + u)*Sn + tid;
        #pragma unroll
        for (int i = 0; i < CIN/2; i++) {
            float lo = sp[(size_t)(2*i)*Sn*Sn];
            float hi = sp[(size_t)(2*i+1)*Sn*Sn];
            rp[i] = pk2p(lo, hi);
        }
        if (CIN & 1) rtail = sp[(size_t)(CIN-1)*Sn*Sn];
    }
    __syncthreads();
    #pragma unroll 1
    for (int co = 0; co < 32; co += 2) {
        const ulonglong2* gA = (const ulonglong2*)(sG + co*48);
        const ulonglong2* gB = (const ulonglong2*)(sG + (co+1)*48);
        const ulonglong2* wA = (const ulonglong2*)(scw + co*36);
        const ulonglong2* wB = (const ulonglong2*)(scw + (co+1)*36);
        unsigned long long aP0 = pk2p(scb[co], 0.f),   aP1 = 0ull;
        unsigned long long bP0 = pk2p(scb[co+1], 0.f), bP1 = 0ull;
        #pragma unroll
        for (int j4 = 0; j4 < 12; j4++) {
            ulonglong2 ga = gA[j4], gb = gB[j4];
            fma2(aP0, ga.x, wrp[2*j4]);
            fma2(aP1, ga.y, wrp[2*j4+1]);
            fma2(bP0, gb.x, wrp[2*j4]);
            fma2(bP1, gb.y, wrp[2*j4+1]);
        }
        #pragma unroll
        for (int c4 = 0; c4 < CIN/4; c4++) {
            ulonglong2 wa = wA[c4], wb = wB[c4];
            fma2(aP0, rp[2*c4], wa.x);
            fma2(aP1, rp[2*c4+1], wa.y);
            fma2(bP0, rp[2*c4], wb.x);
            fma2(bP1, rp[2*c4+1], wb.y);
        }
        float a0, a1, a2, a3, b0, b1, b2, b3;
        up2(aP0, a0, a1); up2(aP1, a2, a3);
        up2(bP0, b0, b1); up2(bP1, b2, b3);
        if (CIN & 1) {
            a0 += rtail*scw[co*36 + (CIN-1)];
            b0 += rtail*scw[(co+1)*36 + (CIN-1)];
        }
        float accA = (a0 + a1) + (a2 + a3);
        float accB = (b0 + b1) + (b2 + b3);
        if (DOGELU) {
            accA = fast_gelu(accA);
            accB = fast_gelu(accB);
        }
        dst[(((size_t)b*WID + co)*Sn + u)*Sn + tid] = accA;
        dst[(((size_t)b*WID + co+1)*Sn + u)*Sn + tid] = accB;
    }
}

// -------- fused fc1 + gelu + fc2; FFMA2 inner loop, 2 u-rows per block --------
__global__ __launch_bounds__(256) void k_fc12(const float* __restrict__ w1, const float* __restrict__ b1,
                       const float* __restrict__ w2, const float* __restrict__ b2,
                       float* __restrict__ out) {
    __shared__ float sW1t[128*32];   // [k][c], rows 128B (16B-aligned)
    __shared__ float sW2[128];
    __shared__ float sB1[128];
    int tid = threadIdx.x;
    for (int i = tid; i < 4096; i += 256) {
        int c = i / 128, k = i % 128;
        sW1t[k*32 + c] = w1[i];
    }
    if (tid < 128) { sW2[tid] = w2[tid]; sB1[tid] = b1[tid]; }
    __syncthreads();
    int u0 = blockIdx.x*2, b = blockIdx.y, v = tid;
    unsigned long long hp0[16], hp1[16];
    #pragma unroll
    for (int c2 = 0; c2 < 16; c2++) {
        const float* hpa = g_h0 + (((size_t)b*WID + 2*c2)*Sn + u0)*Sn + v;
        const float* hpb = g_h0 + (((size_t)b*WID + 2*c2+1)*Sn + u0)*Sn + v;
        hp0[c2] = pk2p(hpa[0], hpb[0]);
        hp1[c2] = pk2p(hpa[Sn], hpb[Sn]);
    }
    float o0 = b2[0], o1 = b2[0];
    #pragma unroll 2
    for (int k = 0; k < 128; k++) {
        const ulonglong2* wk = (const ulonglong2*)(sW1t + k*32);
        unsigned long long zP0 = pk2p(sB1[k], 0.f), zP1 = 0ull;
        unsigned long long yP0 = pk2p(sB1[k], 0.f), yP1 = 0ull;
        #pragma unroll
        for (int c4 = 0; c4 < 8; c4++) {
            ulonglong2 w = wk[c4];
            fma2(zP0, hp0[2*c4],   w.x);
            fma2(zP1, hp0[2*c4+1], w.y);
            fma2(yP0, hp1[2*c4],   w.x);
            fma2(yP1, hp1[2*c4+1], w.y);
        }
        float z0, z1, z2, z3, y0, y1, y2, y3;
        up2(zP0, z0, z1); up2(zP1, z2, z3);
        up2(yP0, y0, y1); up2(yP1, y2, y3);
        float z = fast_gelu((z0 + z1) + (z2 + z3));
        float y = fast_gelu((y0 + y1) + (y2 + y3));
        o0 += z*sW2[k];
        o1 += y*sW2[k];
    }
    out[((size_t)b*Sn + u0)*Sn + v]     = o0;
    out[((size_t)b*Sn + u0 + 1)*Sn + v] = o1;
}

// -------- host --------
extern "C" void kernel_launch(void* const* d_in, const int* in_sizes, int n_in,
                              void* d_out, int out_size) {
    const float* x    = (const float*)d_in[0];
    const float* ap   = (const float*)d_in[1];
    const float* fc0w = (const float*)d_in[2];
    const float* fc0b = (const float*)d_in[3];
    const float* rb[4] = {(const float*)d_in[4], (const float*)d_in[5],
                          (const float*)d_in[6], (const float*)d_in[7]};
    const float* cw[4] = {(const float*)d_in[8],  (const float*)d_in[10],
                          (const float*)d_in[12], (const float*)d_in[14]};
    const float* cb[4] = {(const float*)d_in[9],  (const float*)d_in[11],
                          (const float*)d_in[13], (const float*)d_in[15]};
    const float* fc1w = (const float*)d_in[16];
    const float* fc1b = (const float*)d_in[17];
    const float* fc2w = (const float*)d_in[18];
    const float* fc2b = (const float*)d_in[19];
    float* out = (float*)d_out;

    float *h0, *h1;
    cudaGetSymbolAddress((void**)&h0, g_h0);
    cudaGetSymbolAddress((void**)&h1, g_h1);

    cudaFuncSetAttribute(k_ff, cudaFuncAttributeMaxDynamicSharedMemorySize, SM_FF);
    cudaFuncSetAttribute(k_i1, cudaFuncAttributeMaxDynamicSharedMemorySize, SM_I1);

    k_init<<<256, 48>>>();
    k_wprep<<<dim3(256, 4), 256>>>(rb[0], rb[1], rb[2], rb[3]);
    k_fc0<<<dim3(Sn, Bn), 256>>>(x, ap, fc0w, fc0b);

    float* bufs[5] = {h0, h1, h0, h1, h0};
    for (int blk = 0; blk < 4; blk++) {
        int Cin = (blk == 0) ? 33 : 32;
        k_ff<<<Bn*Cin, 256, SM_FF>>>(bufs[blk]);
        k_mix<<<dim3(NM/4, Bn), 128>>>(Cin, blk);
        k_i1<<<Bn*WID, 256, SM_I1>>>();
        if (blk == 0)
            k_i2<33,true><<<dim3(Sn, Bn), 256>>>(bufs[0], bufs[1], cw[0], cb[0]);
        else if (blk < 3)
            k_i2<32,true><<<dim3(Sn, Bn), 256>>>(bufs[blk], bufs[blk+1], cw[blk], cb[blk]);
        else
            k_i2<32,false><<<dim3(Sn, Bn), 256>>>(bufs[3], bufs[4], cw[3], cb[3]);
    }
    k_fc12<<<dim3(Sn/2, Bn), 256>>>(fc1w, fc1b, fc2w, fc2b, out);
}